// round 12
// baseline (speedup 1.0000x reference)
#include <cuda_runtime.h>

#define HID  128
#define NIN  64
#define NOUT 64
#define NB   256
#define NS   4096

typedef unsigned long long u64;

// xp[b][s][jp] = {xp[2jp], xp[2jp+1]} (bias folded). 512 MB.
__device__ u64 g_xp[NB][NS][HID / 2];
// hs[b][s][jp] = {h[2jp], h[2jp+1]}. 512 MB.
__device__ u64 g_hs[NB][NS][HID / 2];

__device__ __forceinline__ u64 ffma2(u64 a, u64 b, u64 c) {
    u64 d;
    asm("fma.rn.f32x2 %0, %1, %2, %3;" : "=l"(d) : "l"(a), "l"(b), "l"(c));
    return d;
}
__device__ __forceinline__ u64 fadd2(u64 a, u64 b) {
    u64 d;
    asm("add.rn.f32x2 %0, %1, %2;" : "=l"(d) : "l"(a), "l"(b));
    return d;
}
__device__ __forceinline__ u64 pack2(float x, float y) {
    u64 d;
    asm("mov.b64 %0, {%1, %2};" : "=l"(d) : "f"(x), "f"(y));
    return d;
}
__device__ __forceinline__ float2 unpack2(u64 v) {
    float2 r;
    asm("mov.b64 {%0, %1}, %2;" : "=f"(r.x), "=f"(r.y) : "l"(v));
    return r;
}
__device__ __forceinline__ u64 shfl_xor64(u64 v, int m) {
    return __shfl_xor_sync(0xffffffffu, v, m);
}
// dup-h skew: 2-u64 pad per 32-u64 block -> kq slices on banks 0/4/8/12
#define KSK(k) ((k) + (((k) >> 5) << 1))

// ---------------------------------------------------------------------------
// Fused kernel: phase A (x-projection, own rows) then phase B (recurrence).
// Grid: 128 CTAs x 256 thr (1 CTA/SM). Two independent 128-thread row-groups
// (named barriers), group g handles row b = 2*blockIdx.x + g.
//
// Phase A: thread (ajp = u>>1, aih = u&1); wxa[32] u64 (64 regs) register-
// resident; per 16-step tile: cooperative dup-x smem tile, 16 dots each
// reduced with one shfl_xor(1); xp (incl. bh+bx) streamed to g_xp.
//
// Phase B (j-quad / k-quarter): thread (jq = u>>2, kq = u&3) computes
// h[4jq..4jq+3] partials over k in [32kq, 32kq+32). Wh in regs: whd0/whd1[32]
// (128 regs). Per step: 16 LDS.128 (dup h) + 1 LDS.128 (xp) + 2 chains of
// 32 FFMA2 + shfl_xor(1),(2) on both accs + kq0 tail (dup-STS h, STG g_hs)
// + one 128-thread named barrier.  MIO ops/SM/step ~208 (R8: ~408).
// xp read from g_xp via 2-slot/4-step smem ring (1-block LDG slack).
// ---------------------------------------------------------------------------
__global__ void __launch_bounds__(256, 1) rnn_fused(
    const float* __restrict__ x,  const float* __restrict__ Wh,
    const float* __restrict__ bh, const float* __restrict__ Wx,
    const float* __restrict__ bx)
{
    __shared__ __align__(16) u64 xt[2][16][68];     // phase A dup-x tiles
    __shared__ __align__(16) u64 hbuf[2][2][134];   // [grp][buf][dup-h, skewed]
    __shared__ __align__(16) u64 xs[2][2][4][64];   // [grp][slot][st][jp]

    const int tid = threadIdx.x;
    const int g   = tid >> 7;
    const int u   = tid & 127;
    const int b   = blockIdx.x * 2 + g;
    const int bar = g + 1;

    // ======================= Phase A: xp = x@Wx + bh + bx =======================
    {
        const int ajp = u >> 1;       // 0..63 j-pair
        const int aih = u & 1;        // i-half (lane bit 0)
        const int aj0 = 2 * ajp;

        u64 wxa[32];
#pragma unroll
        for (int m = 0; m < 32; m++)
            wxa[m] = *(const u64*)(Wx + (aih * 32 + m) * HID + aj0);
        u64 bias2 = 0;
        if (aih == 0)
            bias2 = pack2(bh[aj0] + bx[aj0], bh[aj0 + 1] + bx[aj0 + 1]);

        const float* xb = x + (long long)b * NS * NIN;
        for (int ts = 0; ts < NS / 16; ts++) {
            // Cooperative dup-x tile: 16 s x 64 i, 8 floats/thread, coalesced.
#pragma unroll
            for (int q = 0; q < 8; q++) {
                int idx = u + q * 128;
                int s = idx >> 6, i = idx & 63;
                float v = xb[(long long)(ts * 16 + s) * NIN + i];
                xt[g][s][i + ((i >> 5) << 1)] = pack2(v, v);
            }
            asm volatile("bar.sync %0, 128;" :: "r"(bar) : "memory");

#pragma unroll 2
            for (int s = 0; s < 16; s++) {
                const u64* xrow = &xt[g][s][aih * 34];
                u64 a = bias2, bb = 0;
#pragma unroll
                for (int m = 0; m < 32; m += 2) {
                    ulonglong2 xv = *(const ulonglong2*)(xrow + m);
                    a  = ffma2(wxa[m],     xv.x, a);
                    bb = ffma2(wxa[m + 1], xv.y, bb);
                }
                a = fadd2(a, bb);
                a = fadd2(a, shfl_xor64(a, 1));
                if (aih == 0) g_xp[b][ts * 16 + s][ajp] = a;
            }
            asm volatile("bar.sync %0, 128;" :: "r"(bar) : "memory");
        }
    }
    // Visibility of own g_xp STGs to phase B LDGs (block-scope fence).
    __syncthreads();

    // ======================= Phase B: recurrence =======================
    const int jq = u >> 2;        // 0..31 j-quad
    const int kq = u & 3;         // k-quarter (lane bits 0,1)
    const int j0 = 4 * jq;

    // Wh slices: one LDG.128 per k covers all 4 j.
    u64 whd0[32], whd1[32];
#pragma unroll
    for (int m = 0; m < 32; m++) {
        ulonglong2 wv = *(const ulonglong2*)(Wh + (kq * 32 + m) * HID + j0);
        whd0[m] = wv.x;           // {Wh[k][j0],   Wh[k][j0+1]}
        whd1[m] = wv.y;           // {Wh[k][j0+2], Wh[k][j0+3]}
    }

    // xp stager mapping: thread u stages ul2 (st_ld, jp_ld..jp_ld+1).
    const int st_ld = u >> 5;          // 0..3
    const int jp_ld = (u & 31) * 2;    // 0..62

    // Init h(0)=0 (dup buffer 0) and zero pads.
    for (int i2 = u; i2 < 134; i2 += 128) hbuf[g][0][i2] = 0ull;

    // Stage xp block 0; prefetch block 1.
    *(ulonglong2*)&xs[g][0][st_ld][jp_ld] =
        *(const ulonglong2*)&g_xp[b][st_ld][jp_ld];
    ulonglong2 xr = *(const ulonglong2*)&g_xp[b][4 + st_ld][jp_ld];
    asm volatile("bar.sync %0, 128;" :: "r"(bar) : "memory");

    const int B1 = NS >> 2;
    for (int bc = 0; bc < B1; bc++) {
        // Block head: stage xp block bc+1 (slot freed after block bc-1),
        // prefetch block bc+2.
        if (4 * (bc + 1) < NS)
            *(ulonglong2*)&xs[g][(bc + 1) & 1][st_ld][jp_ld] = xr;
        if (4 * (bc + 2) < NS)
            xr = *(const ulonglong2*)&g_xp[b][4 * (bc + 2) + st_ld][jp_ld];

#pragma unroll
        for (int st = 0; st < 4; st++) {
            const int cur = st & 1, nxt = cur ^ 1;   // s = 4bc+st, s&1 == st&1

            u64 c0, c1;
            if (kq == 0) {
                ulonglong2 xpv = *(const ulonglong2*)&xs[g][bc & 1][st][2 * jq];
                c0 = xpv.x;       // xp (incl. bias) for jp0
                c1 = xpv.y;       // xp for jp1
            } else {
                c0 = 0; c1 = 0;
            }
            const u64* hb = &hbuf[g][cur][kq * 34];
#pragma unroll
            for (int m = 0; m < 32; m += 2) {
                ulonglong2 hv = *(const ulonglong2*)(hb + m);   // dup {h_k},{h_k1}
                c0 = ffma2(whd0[m],     hv.x, c0);
                c1 = ffma2(whd1[m],     hv.x, c1);
                c0 = ffma2(whd0[m + 1], hv.y, c0);
                c1 = ffma2(whd1[m + 1], hv.y, c1);
            }
            // reduce k-quarters (lane bits 0,1)
            c0 = fadd2(c0, shfl_xor64(c0, 1));
            c1 = fadd2(c1, shfl_xor64(c1, 1));
            c0 = fadd2(c0, shfl_xor64(c0, 2));
            c1 = fadd2(c1, shfl_xor64(c1, 2));

            if (kq == 0) {
                float2 t0 = unpack2(c0), t1 = unpack2(c1);
                t0.x = fmaxf(t0.x, 0.f);  t0.y = fmaxf(t0.y, 0.f);
                t1.x = fmaxf(t1.x, 0.f);  t1.y = fmaxf(t1.y, 0.f);
                ulonglong2 w2;
                w2.x = pack2(t0.x, t0.x); w2.y = pack2(t0.y, t0.y);
                *(ulonglong2*)&hbuf[g][nxt][KSK(j0)] = w2;      // dup j0,j0+1
                w2.x = pack2(t1.x, t1.x); w2.y = pack2(t1.y, t1.y);
                *(ulonglong2*)&hbuf[g][nxt][KSK(j0) + 2] = w2;  // dup j0+2,j0+3
                ulonglong2 hc;
                hc.x = pack2(t0.x, t0.y);
                hc.y = pack2(t1.x, t1.y);
                *(ulonglong2*)&g_hs[b][4 * bc + st][2 * jq] = hc;  // STG.128
            }
            asm volatile("bar.sync %0, 128;" :: "r"(bar) : "memory");
        }
    }
}

// ---------------------------------------------------------------------------
// Output: out[b][s][o] = hs[b][s]@Wy + by.  (unchanged, known-good)
// ---------------------------------------------------------------------------
__global__ void __launch_bounds__(256) rnn_output(
    const float* __restrict__ Wy, const float* __restrict__ by,
    float* __restrict__ out)
{
    __shared__ __align__(16) u64   hst[16][72];   // skewed, max index 69
    __shared__ __align__(16) float ot[16][64];

    const int t  = threadIdx.x;
    const int o  = t >> 2;
    const int jq = t & 3;
    const int b  = blockIdx.y;
    const int s0 = blockIdx.x * 16;

    u64 wyp[16];
#pragma unroll
    for (int m = 0; m < 16; m++) {
        int jpp = jq * 16 + m;
        wyp[m] = pack2(Wy[(2 * jpp) * NOUT + o], Wy[(2 * jpp + 1) * NOUT + o]);
    }
    float byv = by[o];

#pragma unroll
    for (int q = 0; q < 4; q++) {
        int idx = t + q * 256;
        int s = idx >> 6, jj = idx & 63;
        hst[s][jj + ((jj >> 4) << 1)] = g_hs[b][s0 + s][jj];
    }
    __syncthreads();

#pragma unroll 4
    for (int s = 0; s < 16; s++) {
        const u64* hrow = &hst[s][jq * 18];
        u64 accA = 0, accB = 0;
#pragma unroll
        for (int m = 0; m < 16; m += 2) {
            ulonglong2 hv = *(const ulonglong2*)(hrow + m);
            accA = ffma2(wyp[m],     hv.x, accA);
            accB = ffma2(wyp[m + 1], hv.y, accB);
        }
        u64 acc = fadd2(accA, accB);
        acc = fadd2(acc, shfl_xor64(acc, 1));
        acc = fadd2(acc, shfl_xor64(acc, 2));
        if (jq == 0) {
            float2 a = unpack2(acc);
            ot[s][o] = a.x + a.y + byv;
        }
    }
    __syncthreads();

#pragma unroll
    for (int q = 0; q < 4; q++) {
        int idx = t + q * 256;
        int s = idx >> 6, oo = idx & 63;
        out[((long long)b * NS + s0 + s) * NOUT + oo] = ot[s][oo];
    }
}

extern "C" void kernel_launch(void* const* d_in, const int* in_sizes, int n_in,
                              void* d_out, int out_size)
{
    const float* x  = (const float*)d_in[0];
    const float* Wh = (const float*)d_in[1];
    const float* bh = (const float*)d_in[2];
    const float* Wx = (const float*)d_in[3];
    const float* bx = (const float*)d_in[4];
    const float* Wy = (const float*)d_in[5];
    const float* by = (const float*)d_in[6];
    float* out = (float*)d_out;

    rnn_fused<<<NB / 2, 256>>>(x, Wh, bh, Wx, bx);
    rnn_output<<<dim3(NS / 16, NB), 256>>>(Wy, by, out);
}

// round 13
// speedup vs baseline: 1.4452x; 1.4452x over previous
#include <cuda_runtime.h>

#define HID  128
#define NIN  64
#define NOUT 64
#define NB   256
#define NS   4096

// xp[b][s][j] = x@Wx + bh + bx (bias folded), float. 512 MB.
__device__ float g_xp[NB][NS][HID];
// hs[b][s][j], float. 512 MB.
__device__ float g_hs[NB][NS][HID];

// ---------------------------------------------------------------------------
// Kernel 1: xp = x@Wx + bh + bx.  Pure scalar FFMA, no reductions.
// Grid (NS/32, NB), 256 thr. Thread t: j = t&127 (output col), sh = t>>7
// (16 steps each). Wx column j register-resident (64 regs). x tile broadcast
// from smem via float4 (all lanes read the same address -> conflict-free).
// ---------------------------------------------------------------------------
__global__ void __launch_bounds__(256) xp_kernel(
    const float* __restrict__ x,  const float* __restrict__ Wx,
    const float* __restrict__ bh, const float* __restrict__ bx)
{
    __shared__ __align__(16) float xt[32][64];

    const int t  = threadIdx.x;
    const int j  = t & 127;
    const int sh = t >> 7;
    const int b  = blockIdx.y;
    const int s0 = blockIdx.x * 32;

    float wxc[64];
#pragma unroll
    for (int i = 0; i < 64; i++)
        wxc[i] = Wx[i * HID + j];          // coalesced across lanes
    const float bsum = bh[j] + bx[j];

    // Cooperative x tile load: 32 s x 64 i = 512 float4, 2 per thread.
#pragma unroll
    for (int q = 0; q < 2; q++) {
        int idx4 = t + q * 256;
        int s  = idx4 >> 4;
        int i4 = (idx4 & 15) * 4;
        *(float4*)&xt[s][i4] =
            *(const float4*)&x[((long long)b * NS + s0 + s) * NIN + i4];
    }
    __syncthreads();

#pragma unroll 2
    for (int ss = 0; ss < 16; ss++) {
        int s = sh * 16 + ss;
        float a0 = bsum, a1 = 0.f, a2 = 0.f, a3 = 0.f;
#pragma unroll
        for (int m = 0; m < 64; m += 4) {
            float4 xv = *(const float4*)&xt[s][m];   // broadcast
            a0 = fmaf(wxc[m],     xv.x, a0);
            a1 = fmaf(wxc[m + 1], xv.y, a1);
            a2 = fmaf(wxc[m + 2], xv.z, a2);
            a3 = fmaf(wxc[m + 3], xv.w, a3);
        }
        g_xp[b][s0 + s][j] = (a0 + a1) + (a2 + a3);  // coalesced 128B/warp
    }
}

// ---------------------------------------------------------------------------
// Kernel 2: recurrence chunk [s0,s1), s0/s1 % 4 == 0.  Pure scalar.
// Grid: 128 CTAs x 256 thr. Two independent 128-thread row-groups per CTA
// (named barriers), group g owns row b = 2*blockIdx.x + g.
// Thread u computes the FULL h[u]: Wh column u in 128 regs, h(s-1) broadcast
// from smem (float4), xp(s) from a 2-slot/4-step smem ring.
// NO reduction, NO divergence: tail = relu + scalar STS + scalar STG + bar.
// ---------------------------------------------------------------------------
__global__ void __launch_bounds__(256, 1) rnn_rec_chunk(
    const float* __restrict__ Wh, int s0, int s1)
{
    __shared__ __align__(16) float hbufF[2][2][HID];     // [grp][buf][j]
    __shared__ __align__(16) float xsr[2][2][4][HID];    // [grp][slot][st][j]

    const int tid = threadIdx.x;
    const int g   = tid >> 7;
    const int u   = tid & 127;
    const int b   = blockIdx.x * 2 + g;
    const int bar = g + 1;

    // Wh column u: 128 regs, coalesced loads across lanes.
    float whc[128];
#pragma unroll
    for (int k = 0; k < 128; k++)
        whc[k] = Wh[k * HID + u];

    // xp stager mapping: one float4 per thread covers a 4-step block.
    const int st_ld = u >> 5;          // 0..3
    const int j4    = (u & 31) * 4;    // 0..124

    const int B0 = s0 >> 2, B1 = s1 >> 2;

    // Prologue: h(s0-1), stage xp block B0, prefetch B0+1.
    hbufF[g][0][u] = (s0 == 0) ? 0.f : g_hs[b][s0 - 1][u];
    *(float4*)&xsr[g][B0 & 1][st_ld][j4] =
        *(const float4*)&g_xp[b][4 * B0 + st_ld][j4];
    float4 xr = make_float4(0.f, 0.f, 0.f, 0.f);
    if (4 * (B0 + 1) < NS)
        xr = *(const float4*)&g_xp[b][4 * (B0 + 1) + st_ld][j4];
    asm volatile("bar.sync %0, 128;" :: "r"(bar) : "memory");

    for (int bc = B0; bc < B1; bc++) {
        // Block head: stage xp block bc+1 (slot last read in block bc-1),
        // prefetch block bc+2.
        if (4 * (bc + 1) < NS)
            *(float4*)&xsr[g][(bc + 1) & 1][st_ld][j4] = xr;
        if (4 * (bc + 2) < NS)
            xr = *(const float4*)&g_xp[b][4 * (bc + 2) + st_ld][j4];

#pragma unroll
        for (int st = 0; st < 4; st++) {
            const int cur = st & 1, nxt = cur ^ 1;   // 4bc even -> s&1 == st&1

            float a0 = xsr[g][bc & 1][st][u];        // xp incl. bias
            float a1 = 0.f, a2 = 0.f, a3 = 0.f;
            const float* hb = hbufF[g][cur];
#pragma unroll
            for (int m = 0; m < 128; m += 4) {
                float4 hv = *(const float4*)(hb + m);   // broadcast
                a0 = fmaf(whc[m],     hv.x, a0);
                a1 = fmaf(whc[m + 1], hv.y, a1);
                a2 = fmaf(whc[m + 2], hv.z, a2);
                a3 = fmaf(whc[m + 3], hv.w, a3);
            }
            float h = fmaxf((a0 + a1) + (a2 + a3), 0.f);
            hbufF[g][nxt][u] = h;                    // conflict-free STS
            g_hs[b][4 * bc + st][u] = h;             // coalesced 512B STG
            asm volatile("bar.sync %0, 128;" :: "r"(bar) : "memory");
        }
    }
}

// ---------------------------------------------------------------------------
// Kernel 3: out[b][s][o] = hs[b][s]@Wy + by.  Pure scalar, no reductions.
// Grid (NS/32, NB), 256 thr. Thread t: o = t&63, q = t>>6 (8 steps each).
// Wy column o in 128 regs; hs tile broadcast from smem via float4.
// ---------------------------------------------------------------------------
__global__ void __launch_bounds__(256) rnn_output(
    const float* __restrict__ Wy, const float* __restrict__ by,
    float* __restrict__ out)
{
    __shared__ __align__(16) float hst[32][HID];   // 16 KB

    const int t  = threadIdx.x;
    const int o  = t & 63;
    const int q  = t >> 6;
    const int b  = blockIdx.y;
    const int s0 = blockIdx.x * 32;

    float wyc[128];
#pragma unroll
    for (int k = 0; k < 128; k++)
        wyc[k] = Wy[k * NOUT + o];
    const float byv = by[o];

    // Cooperative hs tile load: 32 s x 128 j = 1024 float4, 4 per thread.
#pragma unroll
    for (int qq = 0; qq < 4; qq++) {
        int idx4 = t + qq * 256;
        int s  = idx4 >> 5;
        int jj = (idx4 & 31) * 4;
        *(float4*)&hst[s][jj] = *(const float4*)&g_hs[b][s0 + s][jj];
    }
    __syncthreads();

#pragma unroll 2
    for (int ss = 0; ss < 8; ss++) {
        int s = q * 8 + ss;
        float a0 = byv, a1 = 0.f, a2 = 0.f, a3 = 0.f;
#pragma unroll
        for (int m = 0; m < 128; m += 4) {
            float4 hv = *(const float4*)&hst[s][m];  // broadcast
            a0 = fmaf(wyc[m],     hv.x, a0);
            a1 = fmaf(wyc[m + 1], hv.y, a1);
            a2 = fmaf(wyc[m + 2], hv.z, a2);
            a3 = fmaf(wyc[m + 3], hv.w, a3);
        }
        out[((long long)b * NS + s0 + s) * NOUT + o] = (a0 + a1) + (a2 + a3);
    }
}

extern "C" void kernel_launch(void* const* d_in, const int* in_sizes, int n_in,
                              void* d_out, int out_size)
{
    const float* x  = (const float*)d_in[0];
    const float* Wh = (const float*)d_in[1];
    const float* bh = (const float*)d_in[2];
    const float* Wx = (const float*)d_in[3];
    const float* bx = (const float*)d_in[4];
    const float* Wy = (const float*)d_in[5];
    const float* by = (const float*)d_in[6];
    float* out = (float*)d_out;

    xp_kernel<<<dim3(NS / 32, NB), 256>>>(x, Wx, bh, bx);
    rnn_rec_chunk<<<NB / 2, 256>>>(Wh,    0, 1364);
    rnn_rec_chunk<<<NB / 2, 256>>>(Wh, 1364, 2732);
    rnn_rec_chunk<<<NB / 2, 256>>>(Wh, 2732, 4096);
    rnn_output<<<dim3(NS / 32, NB), 256>>>(Wy, by, out);
}

// round 14
// speedup vs baseline: 1.5125x; 1.0466x over previous
#include <cuda_runtime.h>

#define HID  128
#define NIN  64
#define NOUT 64
#define NB   256
#define NS   4096

// xp[b][s][j] = x@Wx + bh + bx (bias folded), float. 512 MB.
__device__ float g_xp[NB][NS][HID];
// hs[b][s][j], float. 512 MB.
__device__ float g_hs[NB][NS][HID];

// ---------------------------------------------------------------------------
// Kernel 1: xp = x@Wx + bh + bx for s in [s_base, s_base + 32*gridDim.x).
// 128 threads (co-residency-sized: ~80 regs). Thread j = t owns column j.
// ---------------------------------------------------------------------------
__global__ void __launch_bounds__(128) xp_kernel(
    const float* __restrict__ x,  const float* __restrict__ Wx,
    const float* __restrict__ bh, const float* __restrict__ bx, int s_base)
{
    __shared__ __align__(16) float xt[32][64];

    const int t  = threadIdx.x;
    const int j  = t;
    const int b  = blockIdx.y;
    const int s0 = s_base + blockIdx.x * 32;

    float wxc[64];
#pragma unroll
    for (int i = 0; i < 64; i++)
        wxc[i] = Wx[i * HID + j];
    const float bsum = bh[j] + bx[j];

    // Tile load: 32 s x 64 i = 512 float4, 4 per thread, coalesced.
#pragma unroll
    for (int q = 0; q < 4; q++) {
        int idx4 = t + q * 128;
        int s  = idx4 >> 4;
        int i4 = (idx4 & 15) * 4;
        *(float4*)&xt[s][i4] =
            *(const float4*)&x[((long long)b * NS + s0 + s) * NIN + i4];
    }
    __syncthreads();

#pragma unroll 2
    for (int s = 0; s < 32; s++) {
        float a0 = bsum, a1 = 0.f, a2 = 0.f, a3 = 0.f;
#pragma unroll
        for (int m = 0; m < 64; m += 4) {
            float4 xv = *(const float4*)&xt[s][m];   // broadcast
            a0 = fmaf(wxc[m],     xv.x, a0);
            a1 = fmaf(wxc[m + 1], xv.y, a1);
            a2 = fmaf(wxc[m + 2], xv.z, a2);
            a3 = fmaf(wxc[m + 3], xv.w, a3);
        }
        g_xp[b][s0 + s][j] = (a0 + a1) + (a2 + a3);
    }
}

// ---------------------------------------------------------------------------
// Kernel 2: recurrence chunk [s0,s1), s0/s1 % 4 == 0.  (R13, unchanged)
// ---------------------------------------------------------------------------
__global__ void __launch_bounds__(256, 1) rnn_rec_chunk(
    const float* __restrict__ Wh, int s0, int s1)
{
    __shared__ __align__(16) float hbufF[2][2][HID];     // [grp][buf][j]
    __shared__ __align__(16) float xsr[2][2][4][HID];    // [grp][slot][st][j]

    const int tid = threadIdx.x;
    const int g   = tid >> 7;
    const int u   = tid & 127;
    const int b   = blockIdx.x * 2 + g;
    const int bar = g + 1;

    float whc[128];
#pragma unroll
    for (int k = 0; k < 128; k++)
        whc[k] = Wh[k * HID + u];

    const int st_ld = u >> 5;
    const int j4    = (u & 31) * 4;

    const int B0 = s0 >> 2, B1 = s1 >> 2;

    hbufF[g][0][u] = (s0 == 0) ? 0.f : g_hs[b][s0 - 1][u];
    *(float4*)&xsr[g][B0 & 1][st_ld][j4] =
        *(const float4*)&g_xp[b][4 * B0 + st_ld][j4];
    float4 xr = make_float4(0.f, 0.f, 0.f, 0.f);
    if (4 * (B0 + 1) < NS)
        xr = *(const float4*)&g_xp[b][4 * (B0 + 1) + st_ld][j4];
    asm volatile("bar.sync %0, 128;" :: "r"(bar) : "memory");

    for (int bc = B0; bc < B1; bc++) {
        if (4 * (bc + 1) < NS)
            *(float4*)&xsr[g][(bc + 1) & 1][st_ld][j4] = xr;
        if (4 * (bc + 2) < NS)
            xr = *(const float4*)&g_xp[b][4 * (bc + 2) + st_ld][j4];

#pragma unroll
        for (int st = 0; st < 4; st++) {
            const int cur = st & 1, nxt = cur ^ 1;

            float a0 = xsr[g][bc & 1][st][u];
            float a1 = 0.f, a2 = 0.f, a3 = 0.f;
            const float* hb = hbufF[g][cur];
#pragma unroll
            for (int m = 0; m < 128; m += 4) {
                float4 hv = *(const float4*)(hb + m);
                a0 = fmaf(whc[m],     hv.x, a0);
                a1 = fmaf(whc[m + 1], hv.y, a1);
                a2 = fmaf(whc[m + 2], hv.z, a2);
                a3 = fmaf(whc[m + 3], hv.w, a3);
            }
            float h = fmaxf((a0 + a1) + (a2 + a3), 0.f);
            hbufF[g][nxt][u] = h;
            g_hs[b][4 * bc + st][u] = h;
            asm volatile("bar.sync %0, 128;" :: "r"(bar) : "memory");
        }
    }
}

// ---------------------------------------------------------------------------
// Kernel 3: out[b][s][o] = hs[b][s]@Wy + by for s in [s_base, +32*gridDim.x).
// 128 threads (co-residency-sized): o = t>>1, kh = t&1 (k-half), shfl_xor(1).
// ---------------------------------------------------------------------------
__global__ void __launch_bounds__(128) rnn_output(
    const float* __restrict__ Wy, const float* __restrict__ by,
    float* __restrict__ out, int s_base)
{
    __shared__ __align__(16) float hst[32][HID];   // 16 KB

    const int t  = threadIdx.x;
    const int o  = t >> 1;
    const int kh = t & 1;
    const int b  = blockIdx.y;
    const int s0 = s_base + blockIdx.x * 32;

    float wyc[64];
#pragma unroll
    for (int k = 0; k < 64; k++)
        wyc[k] = Wy[(kh * 64 + k) * NOUT + o];
    const float byv = (kh == 0) ? by[o] : 0.f;

    // Tile load: 32 s x 128 j = 1024 float4, 8 per thread, coalesced.
#pragma unroll
    for (int q = 0; q < 8; q++) {
        int idx4 = t + q * 128;
        int s  = idx4 >> 5;
        int jj = (idx4 & 31) * 4;
        *(float4*)&hst[s][jj] = *(const float4*)&g_hs[b][s0 + s][jj];
    }
    __syncthreads();

#pragma unroll 2
    for (int s = 0; s < 32; s++) {
        float a0 = byv, a1 = 0.f, a2 = 0.f, a3 = 0.f;
        const float* hb = &hst[s][kh * 64];
#pragma unroll
        for (int m = 0; m < 64; m += 4) {
            float4 hv = *(const float4*)(hb + m);
            a0 = fmaf(wyc[m],     hv.x, a0);
            a1 = fmaf(wyc[m + 1], hv.y, a1);
            a2 = fmaf(wyc[m + 2], hv.z, a2);
            a3 = fmaf(wyc[m + 3], hv.w, a3);
        }
        float r = (a0 + a1) + (a2 + a3);
        r += __shfl_xor_sync(0xffffffffu, r, 1);   // combine k-halves
        if (kh == 0)
            out[((long long)b * NS + s0 + s) * NOUT + o] = r;
    }
}

// ---------------------------------------------------------------------------
// Two-stream pipeline:
//   main(0): xpA | rec1 | rec2 | rec3 | outC
//   s1:           xpB, xpC, outA, outB   (event fork/join, capture-legal)
// Deps: rec2<-xpB, rec3<-xpC, outA<-rec1, outB<-rec2, outC<-rec3+outAB.
// Ranges: A=[0,1376) B=[1376,2752) C=[2752,4096)  (43/43/42 tiles of 32).
// ---------------------------------------------------------------------------
extern "C" void kernel_launch(void* const* d_in, const int* in_sizes, int n_in,
                              void* d_out, int out_size)
{
    const float* x  = (const float*)d_in[0];
    const float* Wh = (const float*)d_in[1];
    const float* bh = (const float*)d_in[2];
    const float* Wx = (const float*)d_in[3];
    const float* bx = (const float*)d_in[4];
    const float* Wy = (const float*)d_in[5];
    const float* by = (const float*)d_in[6];
    float* out = (float*)d_out;

    static cudaStream_t s1 = nullptr;
    static cudaEvent_t ev0, evB, evC, evR1, evR2, evOut;
    if (s1 == nullptr) {
        cudaStreamCreateWithFlags(&s1, cudaStreamNonBlocking);
        cudaEventCreateWithFlags(&ev0,  cudaEventDisableTiming);
        cudaEventCreateWithFlags(&evB,  cudaEventDisableTiming);
        cudaEventCreateWithFlags(&evC,  cudaEventDisableTiming);
        cudaEventCreateWithFlags(&evR1, cudaEventDisableTiming);
        cudaEventCreateWithFlags(&evR2, cudaEventDisableTiming);
        cudaEventCreateWithFlags(&evOut, cudaEventDisableTiming);
    }

    // xpA on main
    xp_kernel<<<dim3(43, NB), 128>>>(x, Wx, bh, bx, 0);
    cudaEventRecord(ev0, 0);

    // fork: xpB, xpC on s1
    cudaStreamWaitEvent(s1, ev0, 0);
    xp_kernel<<<dim3(43, NB), 128, 0, s1>>>(x, Wx, bh, bx, 1376);
    cudaEventRecord(evB, s1);
    xp_kernel<<<dim3(42, NB), 128, 0, s1>>>(x, Wx, bh, bx, 2752);
    cudaEventRecord(evC, s1);

    // rec1 on main (overlaps xpB/xpC)
    rnn_rec_chunk<<<NB / 2, 256>>>(Wh, 0, 1376);
    cudaEventRecord(evR1, 0);

    // rec2 needs xpB
    cudaStreamWaitEvent(0, evB, 0);
    rnn_rec_chunk<<<NB / 2, 256>>>(Wh, 1376, 2752);
    cudaEventRecord(evR2, 0);

    // outA/outB on s1 (overlap rec2/rec3)
    cudaStreamWaitEvent(s1, evR1, 0);
    rnn_output<<<dim3(43, NB), 128, 0, s1>>>(Wy, by, out, 0);
    cudaStreamWaitEvent(s1, evR2, 0);
    rnn_output<<<dim3(43, NB), 128, 0, s1>>>(Wy, by, out, 1376);
    cudaEventRecord(evOut, s1);

    // rec3 needs xpC
    cudaStreamWaitEvent(0, evC, 0);
    rnn_rec_chunk<<<NB / 2, 256>>>(Wh, 2752, 4096);

    // join + outC on main
    cudaStreamWaitEvent(0, evOut, 0);
    rnn_output<<<dim3(42, NB), 128>>>(Wy, by, out, 2752);
}